// round 2
// baseline (speedup 1.0000x reference)
#include <cuda_runtime.h>
#include <cstdint>

#define BB 16
#define NN 2048
#define MM 1024
#define TT 256

#define IOU_THR 0.5f
#define SCALE_C (4.5392368437151541e-04f)  // 1/sqrt(1920^2+1080^2)
#define A_TRK 2.0f
#define A_SPA 1.5f
#define A_TMP 1.8f
#define B_FP 0.9f
#define B_FN 0.9f
#define G_SW 1.5f

// ---------------- device scratch (no allocations allowed) ----------------
__device__ int   g_gt_cnt[BB][TT];
__device__ int   g_pr_cnt[BB][TT];
__device__ float g_meanw[BB][TT];
__device__ float g_meanh[BB][TT];
__device__ float g_fn[BB];
__device__ int   g_nuni[BB];
__device__ int   g_nvalid[BB];
__device__ float g_match[BB];
__device__ float g_fp[BB];
__device__ int   g_sw[BB];
__device__ float g_spatial[BB];
__device__ float g_temporal[BB];

// ======================= K1: histograms + fn + counts =======================
__global__ __launch_bounds__(256) void k1_hist(
    const float4* __restrict__ pboxes,   // [B][N] float4
    const int*    __restrict__ pid,      // [B][N]
    const int*    __restrict__ gid)      // [B][M]
{
    const int b = blockIdx.x;
    const int tid = threadIdx.x;
    __shared__ int   s_gt[TT];
    __shared__ int   s_pr[TT];
    __shared__ float s_sumw[TT];
    __shared__ float s_sumh[TT];

    s_gt[tid] = 0; s_pr[tid] = 0; s_sumw[tid] = 0.f; s_sumh[tid] = 0.f;
    if (tid == 0) { g_match[b] = 0.f; g_fp[b] = 0.f; g_sw[b] = 0; }
    __syncthreads();

    const int* gidb = gid + b * MM;
    for (int j = tid; j < MM; j += 256)
        atomicAdd(&s_gt[gidb[j]], 1);

    const int* pidb = pid + b * NN;
    const float4* pb = pboxes + b * NN;
    int nvalid = 0;
    for (int i = tid; i < NN; i += 256) {
        int p = pidb[i];
        if (p > 0) {
            float4 bx = pb[i];
            atomicAdd(&s_pr[p], 1);
            atomicAdd(&s_sumw[p], bx.z - bx.x);
            atomicAdd(&s_sumh[p], bx.w - bx.y);
            nvalid++;
        }
    }
    __syncthreads();

    const int t = tid;
    int cnt = s_pr[t];
    int gc  = s_gt[t];
    g_gt_cnt[b][t] = gc;
    g_pr_cnt[b][t] = cnt;
    float cs = fmaxf((float)cnt, 1.f);
    g_meanw[b][t] = s_sumw[t] / cs;
    g_meanh[b][t] = s_sumh[t] / cs;

    float fn = (gc > 0 && cnt == 0) ? (float)gc : 0.f;
    int   nu = (cnt > 0) ? 1 : 0;

    // block reduce fn(float), nu(int), nvalid(int)
    int lane = tid & 31, w = tid >> 5;
    #pragma unroll
    for (int o = 16; o > 0; o >>= 1) {
        fn     += __shfl_down_sync(0xffffffffu, fn, o);
        nu     += __shfl_down_sync(0xffffffffu, nu, o);
        nvalid += __shfl_down_sync(0xffffffffu, nvalid, o);
    }
    __shared__ float r_f[8];
    __shared__ int   r_u[8], r_v[8];
    if (lane == 0) { r_f[w] = fn; r_u[w] = nu; r_v[w] = nvalid; }
    __syncthreads();
    if (tid == 0) {
        float F = 0.f; int U = 0, V = 0;
        #pragma unroll
        for (int k = 0; k < 8; k++) { F += r_f[k]; U += r_u[k]; V += r_v[k]; }
        g_fn[b] = F; g_nuni[b] = U; g_nvalid[b] = V;
    }
}

// ======================= K2: spatial deviation + temporal =======================
__global__ __launch_bounds__(256) void k2_spat_temp(
    const float4* __restrict__ pboxes,
    const int*    __restrict__ pid)
{
    const int b = blockIdx.x;
    const int tid = threadIdx.x;
    __shared__ float s_mw[TT], s_mh[TT], s_sdw[TT], s_sdh[TT];
    __shared__ int   s_pc[TT];
    __shared__ int   s_pid[NN];
    __shared__ float s_cx[NN], s_cy[NN];

    s_mw[tid]  = g_meanw[b][tid];
    s_mh[tid]  = g_meanh[b][tid];
    s_pc[tid]  = g_pr_cnt[b][tid];
    s_sdw[tid] = 0.f; s_sdh[tid] = 0.f;
    __syncthreads();

    const int* pidb = pid + b * NN;
    const float4* pb = pboxes + b * NN;
    for (int i = tid; i < NN; i += 256) {
        int p = pidb[i];
        float4 bx = pb[i];
        s_pid[i] = p;
        s_cx[i] = (bx.x + bx.z) * 0.5f;
        s_cy[i] = (bx.y + bx.w) * 0.5f;
        if (p > 0) {
            atomicAdd(&s_sdw[p], fabsf((bx.z - bx.x) - s_mw[p]));
            atomicAdd(&s_sdh[p], fabsf((bx.w - bx.y) - s_mh[p]));
        }
    }
    __syncthreads();

    // spatial per-track
    const int t = tid;
    int cnt = s_pc[t];
    float sp = 0.f;
    if (cnt > 1) sp = (s_sdw[t] + s_sdh[t]) * SCALE_C / (float)cnt;

    // temporal per-track: scan preds in original order (== stable sort order)
    float tp = 0.f;
    if (t > 0 && cnt > 2) {
        float c0x = 0.f, c0y = 0.f, c1x = 0.f, c1y = 0.f;
        int   seen = 0;
        float sa = 0.f;
        for (int i = 0; i < NN; i++) {
            if (s_pid[i] == t) {
                float cx = s_cx[i], cy = s_cy[i];
                if (seen >= 2) {
                    float ax = (cx - 2.f * c1x + c0x) * SCALE_C;
                    float ay = (cy - 2.f * c1y + c0y) * SCALE_C;
                    sa += sqrtf(ax * ax + ay * ay);
                }
                c0x = c1x; c0y = c1y; c1x = cx; c1y = cy;
                seen++;
            }
        }
        tp = sa / (float)(cnt - 2);
    }

    // reduce sp, tp
    int lane = tid & 31, w = tid >> 5;
    #pragma unroll
    for (int o = 16; o > 0; o >>= 1) {
        sp += __shfl_down_sync(0xffffffffu, sp, o);
        tp += __shfl_down_sync(0xffffffffu, tp, o);
    }
    __shared__ float r_s[8], r_t[8];
    if (lane == 0) { r_s[w] = sp; r_t[w] = tp; }
    __syncthreads();
    if (tid == 0) {
        float S = 0.f, P = 0.f;
        #pragma unroll
        for (int k = 0; k < 8; k++) { S += r_s[k]; P += r_t[k]; }
        int nv = g_nvalid[b];
        int nu = g_nuni[b];
        float inu = 1.f / fmaxf((float)nu, 1.f);
        g_spatial[b]  = (nv > 1) ? S * inu : 0.f;
        g_temporal[b] = (nv > 2) ? P * inu : 0.f;
    }
}

// ======================= K3: IoU sweep (match / switch / fp) =======================
// grid: (NN/128, BB), 256 threads. Two threads per pred, each covers half of M.
__global__ __launch_bounds__(256) void k3_iou(
    const float4* __restrict__ pboxes,
    const float4* __restrict__ gboxes,
    const int*    __restrict__ pid,
    const int*    __restrict__ gid)
{
    const int b = blockIdx.y;
    const int tid = threadIdx.x;
    __shared__ float4 s_gb[MM];      // gt box
    __shared__ float2 s_meta[MM];    // (area, bits = gid | prflag<<8)
    __shared__ int    s_gtc[TT];
    __shared__ float  s_xmi[256];
    __shared__ int    s_xsw[256];

    const float4* gb4 = gboxes + b * MM;
    const int*   gidb = gid + b * MM;
    for (int j = tid; j < MM; j += 256) {
        float4 g = gb4[j];
        s_gb[j] = g;
        float a2 = fmaxf(g.z - g.x, 0.f) * fmaxf(g.w - g.y, 0.f);
        int gj = gidb[j];
        int bits = gj | ((g_pr_cnt[b][gj] > 0) ? 0x100 : 0);
        s_meta[j] = make_float2(a2, __int_as_float(bits));
    }
    if (tid < TT) s_gtc[tid] = g_gt_cnt[b][tid];
    __syncthreads();

    const int pi   = blockIdx.x * 128 + (tid & 127);
    const int half = tid >> 7;
    const int p    = pid[b * NN + pi];
    const bool valid = (p > 0);

    float mi = -1e30f;
    int swc = 0;
    if (valid) {
        float4 pbx = pboxes[b * NN + pi];
        const float px1 = pbx.x, py1 = pbx.y, px2 = pbx.z, py2 = pbx.w;
        const float a1 = fmaxf(px2 - px1, 0.f) * fmaxf(py2 - py1, 0.f);
        const int j0 = half * (MM / 2);
        const int j1 = j0 + (MM / 2);
        #pragma unroll 4
        for (int j = j0; j < j1; j++) {
            float4 g = s_gb[j];
            float2 mt = s_meta[j];
            float lx = fmaxf(px1, g.x), ly = fmaxf(py1, g.y);
            float rx = fminf(px2, g.z), ry = fminf(py2, g.w);
            float iw = fmaxf(rx - lx, 0.f), ih = fmaxf(ry - ly, 0.f);
            float inter = iw * ih;
            float uni = fmaxf(a1 + mt.x - inter, 1e-6f);
            float iou = __fdividef(inter, uni);
            int bits = __float_as_int(mt.y);
            int gidj = bits & 0xFF;
            bool same = (gidj == p);
            if (same) mi = fmaxf(mi, iou);
            if (iou > IOU_THR && !same && (bits & 0x100)) swc++;
        }
    }

    // combine the two halves of each pred
    s_xmi[tid] = mi;
    s_xsw[tid] = swc;
    __syncthreads();

    float matchv = 0.f, fpv = 0.f;
    int   swtot  = 0;
    if (tid < 128) {
        float m = fmaxf(s_xmi[tid], s_xmi[tid + 128]);
        swtot   = s_xsw[tid] + s_xsw[tid + 128];
        if (valid) {
            if (s_gtc[p] > 0) matchv = 1.f - m;
            else              fpv = 1.f;
        }
        // warp reduce (warps 0..3 full)
        #pragma unroll
        for (int o = 16; o > 0; o >>= 1) {
            matchv += __shfl_down_sync(0xffffffffu, matchv, o);
            fpv    += __shfl_down_sync(0xffffffffu, fpv, o);
            swtot  += __shfl_down_sync(0xffffffffu, swtot, o);
        }
        if ((tid & 31) == 0) {
            atomicAdd(&g_match[b], matchv);
            atomicAdd(&g_fp[b], fpv);
            atomicAdd(&g_sw[b], swtot);
        }
    }
}

// ======================= K4: finalize =======================
__global__ void k4_final(float* __restrict__ out)
{
    const int b = threadIdx.x;
    float lt = 0.f, ls = 0.f, lm = 0.f, nt = 0.f;
    if (b < BB) {
        float has = (g_nvalid[b] > 0) ? 1.f : 0.f;
        float tr = B_FN * g_fn[b] + g_match[b] + G_SW * (float)g_sw[b] + B_FP * g_fp[b];
        lt = tr * has;
        ls = g_spatial[b] * has;
        lm = g_temporal[b] * has;
        nt = (float)g_nuni[b] * has;
    }
    #pragma unroll
    for (int o = 16; o > 0; o >>= 1) {
        lt += __shfl_down_sync(0xffffffffu, lt, o);
        ls += __shfl_down_sync(0xffffffffu, ls, o);
        lm += __shfl_down_sync(0xffffffffu, lm, o);
        nt += __shfl_down_sync(0xffffffffu, nt, o);
    }
    if (b == 0) {
        float norm = (nt > 0.f) ? nt : 1.f;
        lt /= norm; ls /= norm; lm /= norm;
        out[0] = A_TRK * lt + A_SPA * ls + A_TMP * lm;
        out[1] = lt;
        out[2] = ls;
        out[3] = lm;
    }
}

// ======================= launch =======================
extern "C" void kernel_launch(void* const* d_in, const int* in_sizes, int n_in,
                              void* d_out, int out_size)
{
    const float4* pb  = (const float4*)d_in[0];  // pred_boxes [16,2048,4] f32
    const float4* gb  = (const float4*)d_in[1];  // gt_boxes   [16,1024,4] f32
    const int*    pid = (const int*)d_in[2];     // pred_track_ids [16,2048] i32
    const int*    gid = (const int*)d_in[3];     // gt_track_ids   [16,1024] i32
    float* out = (float*)d_out;

    k1_hist<<<BB, 256>>>(pb, pid, gid);
    k2_spat_temp<<<BB, 256>>>(pb, pid);
    k3_iou<<<dim3(NN / 128, BB), 256>>>(pb, gb, pid, gid);
    k4_final<<<1, 32>>>(out);
}

// round 3
// speedup vs baseline: 2.2205x; 2.2205x over previous
#include <cuda_runtime.h>
#include <cstdint>

#define BB 16
#define NN 2048
#define MM 1024
#define TT 256

#define IOU_THR 0.5f
#define SCALE_C (4.5392368437151541e-04f)  // 1/sqrt(1920^2+1080^2)
#define A_TRK 2.0f
#define A_SPA 1.5f
#define A_TMP 1.8f
#define B_FP 0.9f
#define B_FN 0.9f
#define G_SW 1.5f

#define K3_BLOCKS_X 8
#define K3_TOTAL_BLOCKS (K3_BLOCKS_X * BB)   // 128

// ---------------- device scratch (no allocations allowed) ----------------
__device__ int   g_gt_cnt[BB][TT];
__device__ int   g_pr_cnt[BB][TT];
__device__ float g_fn[BB];
__device__ int   g_nuni[BB];
__device__ int   g_nvalid[BB];
__device__ float g_match[BB];
__device__ float g_fp[BB];
__device__ int   g_sw[BB];
__device__ float g_spatial[BB];   // fully finalized in K1
__device__ float g_traw[BB];      // sum over tracks of sa/(cnt-2)
__device__ int   g_done;

// ======================= K1: hist + fn + counts + spatial (fused) =======================
__global__ __launch_bounds__(256) void k1_hist(
    const float4* __restrict__ pboxes,   // [B][N]
    const int*    __restrict__ pid,      // [B][N]
    const int*    __restrict__ gid)      // [B][M]
{
    const int b = blockIdx.x;
    const int tid = threadIdx.x;
    __shared__ int   s_gt[TT];
    __shared__ int   s_pr[TT];
    __shared__ float s_mw[TT];   // sums then means
    __shared__ float s_mh[TT];
    __shared__ float s_dw[TT];
    __shared__ float s_dh[TT];
    __shared__ float s_w[NN];
    __shared__ float s_h[NN];
    __shared__ int   s_p[NN];

    s_gt[tid] = 0; s_pr[tid] = 0;
    s_mw[tid] = 0.f; s_mh[tid] = 0.f;
    s_dw[tid] = 0.f; s_dh[tid] = 0.f;
    if (b == 0 && tid == 0) g_done = 0;
    if (tid == 0) { g_match[b] = 0.f; g_fp[b] = 0.f; g_sw[b] = 0; g_traw[b] = 0.f; }
    __syncthreads();

    const int* gidb = gid + b * MM;
    for (int j = tid; j < MM; j += 256)
        atomicAdd(&s_gt[gidb[j]], 1);

    const int* pidb = pid + b * NN;
    const float4* pb = pboxes + b * NN;
    int nvalid = 0;
    for (int i = tid; i < NN; i += 256) {
        int p = pidb[i];
        float4 bx = pb[i];
        float w = bx.z - bx.x, h = bx.w - bx.y;
        s_w[i] = w; s_h[i] = h; s_p[i] = p;
        if (p > 0) {
            atomicAdd(&s_pr[p], 1);
            atomicAdd(&s_mw[p], w);
            atomicAdd(&s_mh[p], h);
            nvalid++;
        }
    }
    __syncthreads();

    // means in place; publish counts
    {
        int c = s_pr[tid];
        float cs = fmaxf((float)c, 1.f);
        s_mw[tid] = s_mw[tid] / cs;
        s_mh[tid] = s_mh[tid] / cs;
        g_gt_cnt[b][tid] = s_gt[tid];
        g_pr_cnt[b][tid] = c;
    }
    __syncthreads();

    // abs deviation pass
    for (int i = tid; i < NN; i += 256) {
        int p = s_p[i];
        if (p > 0) {
            atomicAdd(&s_dw[p], fabsf(s_w[i] - s_mw[p]));
            atomicAdd(&s_dh[p], fabsf(s_h[i] - s_mh[p]));
        }
    }
    __syncthreads();

    // per-track terms + block reduce
    int c  = s_pr[tid];
    int gc = s_gt[tid];
    float fn = (gc > 0 && c == 0) ? (float)gc : 0.f;
    int   nu = (c > 0) ? 1 : 0;
    float sp = (c > 1) ? (s_dw[tid] + s_dh[tid]) * SCALE_C / (float)c : 0.f;

    int lane = tid & 31, w = tid >> 5;
    #pragma unroll
    for (int o = 16; o > 0; o >>= 1) {
        fn     += __shfl_down_sync(0xffffffffu, fn, o);
        sp     += __shfl_down_sync(0xffffffffu, sp, o);
        nu     += __shfl_down_sync(0xffffffffu, nu, o);
        nvalid += __shfl_down_sync(0xffffffffu, nvalid, o);
    }
    __shared__ float r_f[8], r_s[8];
    __shared__ int   r_u[8], r_v[8];
    if (lane == 0) { r_f[w] = fn; r_s[w] = sp; r_u[w] = nu; r_v[w] = nvalid; }
    __syncthreads();
    if (tid == 0) {
        float F = 0.f, S = 0.f; int U = 0, V = 0;
        #pragma unroll
        for (int k = 0; k < 8; k++) { F += r_f[k]; S += r_s[k]; U += r_u[k]; V += r_v[k]; }
        g_fn[b] = F; g_nuni[b] = U; g_nvalid[b] = V;
        g_spatial[b] = (V > 1) ? S / fmaxf((float)U, 1.f) : 0.f;
    }
}

// ======================= K2: temporal — warp per track, ballot scan =======================
// grid (32, BB), 256 threads (8 warps). warp handles track t = blockIdx.x*8 + warp.
__global__ __launch_bounds__(256) void k2_temporal(
    const float4* __restrict__ pboxes,
    const int*    __restrict__ pid)
{
    const int b = blockIdx.y;
    const int tid = threadIdx.x;
    __shared__ int   s_p[NN];
    __shared__ float s_cx[NN];
    __shared__ float s_cy[NN];

    const int* pidb = pid + b * NN;
    const float4* pb = pboxes + b * NN;
    for (int i = tid; i < NN; i += 256) {
        float4 bx = pb[i];
        s_p[i]  = pidb[i];
        s_cx[i] = (bx.x + bx.z) * 0.5f;
        s_cy[i] = (bx.y + bx.w) * 0.5f;
    }
    __syncthreads();

    const int lane = tid & 31;
    const int t = blockIdx.x * 8 + (tid >> 5);   // 0..255
    if (t == 0) return;                           // id 0 never a track
    const int cnt = g_pr_cnt[b][t];
    if (cnt <= 2) return;

    float c0x = 0.f, c0y = 0.f, c1x = 0.f, c1y = 0.f;
    int seen = 0;
    float sa = 0.f;
    for (int base = 0; base < NN; base += 32) {
        int p = s_p[base + lane];
        unsigned m = __ballot_sync(0xffffffffu, p == t);
        while (m) {
            int j = base + (__ffs(m) - 1);
            m &= m - 1;
            float cx = s_cx[j];   // broadcast (uniform address)
            float cy = s_cy[j];
            if (seen >= 2) {
                float ax = (cx - 2.f * c1x + c0x) * SCALE_C;
                float ay = (cy - 2.f * c1y + c0y) * SCALE_C;
                sa += sqrtf(ax * ax + ay * ay);
            }
            c0x = c1x; c0y = c1y; c1x = cx; c1y = cy;
            seen++;
        }
    }
    if (lane == 0)
        atomicAdd(&g_traw[b], sa / (float)(cnt - 2));
}

// ======================= K3: IoU sweep + fused finalize =======================
// grid (8, BB), 256 threads, one pred per thread over all M gts.
__global__ __launch_bounds__(256) void k3_iou(
    const float4* __restrict__ pboxes,
    const float4* __restrict__ gboxes,
    const int*    __restrict__ pid,
    const int*    __restrict__ gid,
    float* __restrict__ out)
{
    const int b = blockIdx.y;
    const int tid = threadIdx.x;
    __shared__ float4 s_gb[MM];
    __shared__ float2 s_mt[MM];   // x = a2 (sign = pr_cnt>0 flag), y = gid as int bits
    __shared__ int    s_last;

    const float4* gb4 = gboxes + b * MM;
    const int*   gidb = gid + b * MM;
    for (int j = tid; j < MM; j += 256) {
        float4 g = gb4[j];
        s_gb[j] = g;
        float a2 = fmaxf(g.z - g.x, 0.f) * fmaxf(g.w - g.y, 0.f);   // >= 1 for this data
        int gj = gidb[j];
        bool prb = (g_pr_cnt[b][gj] > 0);
        s_mt[j] = make_float2(prb ? a2 : -a2, __int_as_float(gj));
    }
    __syncthreads();

    const int i = blockIdx.x * 256 + tid;
    const int p = pid[b * NN + i];

    float matchv = 0.f, fpv = 0.f;
    int swc = 0;
    if (p > 0) {
        float4 pbx = pboxes[b * NN + i];
        const float px1 = pbx.x, py1 = pbx.y, px2 = pbx.z, py2 = pbx.w;
        const float a1 = fmaxf(px2 - px1, 0.f) * fmaxf(py2 - py1, 0.f);
        float bn = 0.f, bd = 1.f;   // best (inter, union) for same-track max IoU
        #pragma unroll 4
        for (int j = 0; j < MM; j++) {
            float4 g  = s_gb[j];
            float2 mt = s_mt[j];
            float lx = fmaxf(px1, g.x), ly = fmaxf(py1, g.y);
            float rx = fminf(px2, g.z), ry = fminf(py2, g.w);
            float iw = fmaxf(rx - lx, 0.f), ih = fmaxf(ry - ly, 0.f);
            float inter = iw * ih;
            float a2 = fabsf(mt.x);
            float sum = a1 + a2;                      // a1 + a2
            int  gj   = __float_as_int(mt.y);
            bool same = (gj == p);
            // iou > 0.5  <=>  2*inter > union  <=>  3*inter > a1+a2  (union >= 1 here)
            bool hi = (3.f * inter > sum);
            if (hi && !same && (mt.x > 0.f)) swc++;
            if (same) {
                float uni = sum - inter;
                // inter/uni > bn/bd  (all positive)
                if (inter * bd > bn * uni) { bn = inter; bd = uni; }
            }
        }
        float bi = __fdividef(bn, bd);                // 0 if no same gt
        if (g_gt_cnt[b][p] > 0) matchv = 1.f - bi;
        else                    fpv = 1.f;
    }

    // warp reduce, per-warp atomics
    #pragma unroll
    for (int o = 16; o > 0; o >>= 1) {
        matchv += __shfl_down_sync(0xffffffffu, matchv, o);
        fpv    += __shfl_down_sync(0xffffffffu, fpv, o);
        swc    += __shfl_down_sync(0xffffffffu, swc, o);
    }
    if ((tid & 31) == 0) {
        atomicAdd(&g_match[b], matchv);
        atomicAdd(&g_fp[b], fpv);
        atomicAdd(&g_sw[b], swc);
    }

    // ---- last-block-done fused finalize ----
    __syncthreads();
    if (tid == 0) {
        __threadfence();
        int prev = atomicAdd(&g_done, 1);
        s_last = (prev == K3_TOTAL_BLOCKS - 1) ? 1 : 0;
    }
    __syncthreads();
    if (s_last && tid < 32) {
        __threadfence();
        float lt = 0.f, ls = 0.f, lm = 0.f, nt = 0.f;
        if (tid < BB) {
            int bb = tid;
            int nv = g_nvalid[bb];
            int nu = g_nuni[bb];
            float has = (nv > 0) ? 1.f : 0.f;
            float mt  = *((volatile float*)&g_match[bb]);
            float fpb = *((volatile float*)&g_fp[bb]);
            int   sw  = *((volatile int*)&g_sw[bb]);
            float trw = *((volatile float*)&g_traw[bb]);
            float tr = B_FN * g_fn[bb] + mt + G_SW * (float)sw + B_FP * fpb;
            float tmp = (nv > 2) ? trw / fmaxf((float)nu, 1.f) : 0.f;
            lt = tr * has;
            ls = g_spatial[bb] * has;
            lm = tmp * has;
            nt = (float)nu * has;
        }
        #pragma unroll
        for (int o = 16; o > 0; o >>= 1) {
            lt += __shfl_down_sync(0xffffffffu, lt, o);
            ls += __shfl_down_sync(0xffffffffu, ls, o);
            lm += __shfl_down_sync(0xffffffffu, lm, o);
            nt += __shfl_down_sync(0xffffffffu, nt, o);
        }
        if (tid == 0) {
            float norm = (nt > 0.f) ? nt : 1.f;
            lt /= norm; ls /= norm; lm /= norm;
            out[0] = A_TRK * lt + A_SPA * ls + A_TMP * lm;
            out[1] = lt;
            out[2] = ls;
            out[3] = lm;
        }
    }
}

// ======================= launch =======================
extern "C" void kernel_launch(void* const* d_in, const int* in_sizes, int n_in,
                              void* d_out, int out_size)
{
    const float4* pb  = (const float4*)d_in[0];  // pred_boxes [16,2048,4] f32
    const float4* gb  = (const float4*)d_in[1];  // gt_boxes   [16,1024,4] f32
    const int*    pid = (const int*)d_in[2];     // pred_track_ids [16,2048] i32
    const int*    gid = (const int*)d_in[3];     // gt_track_ids   [16,1024] i32
    float* out = (float*)d_out;

    k1_hist<<<BB, 256>>>(pb, pid, gid);
    k2_temporal<<<dim3(32, BB), 256>>>(pb, pid);
    k3_iou<<<dim3(K3_BLOCKS_X, BB), 256>>>(pb, gb, pid, gid, out);
}

// round 4
// speedup vs baseline: 2.5724x; 1.1584x over previous
#include <cuda_runtime.h>
#include <cstdint>

#define BB 16
#define NN 2048
#define MM 1024
#define TT 256

#define SCALE_C (4.5392368437151541e-04f)  // 1/sqrt(1920^2+1080^2)
#define A_TRK 2.0f
#define A_SPA 1.5f
#define A_TMP 1.8f
#define B_FP 0.9f
#define B_FN 0.9f
#define G_SW 1.5f

#define K3_BLOCKS_X 8
#define K3_TOTAL_BLOCKS (K3_BLOCKS_X * BB)   // 128

// ---------------- device scratch (no allocations allowed) ----------------
__device__ int   g_gt_cnt[BB][TT];
__device__ int   g_pr_cnt[BB][TT];
__device__ int   g_csr_off[BB][TT];   // exclusive prefix of gt_cnt
__device__ int   g_csr[BB][MM];       // gt indices grouped by track id
__device__ float g_fn[BB];
__device__ int   g_nuni[BB];
__device__ int   g_nvalid[BB];
__device__ float g_match[BB];
__device__ float g_fp[BB];
__device__ int   g_sw[BB];
__device__ float g_spatial[BB];       // finalized in K1
__device__ float g_traw[BB];          // sum over tracks of sa/(cnt-2)
__device__ int   g_done;

__device__ __forceinline__ float inter_area(float px1, float py1, float px2, float py2,
                                            const float4 g) {
    float lx = fmaxf(px1, g.x), ly = fmaxf(py1, g.y);
    float rx = fminf(px2, g.z), ry = fminf(py2, g.w);
    return fmaxf(rx - lx, 0.f) * fmaxf(ry - ly, 0.f);
}

// ======================= K1: hist + fn + counts + spatial + CSR =======================
__global__ __launch_bounds__(1024) void k1_hist(
    const float4* __restrict__ pboxes,   // [B][N]
    const int*    __restrict__ pid,      // [B][N]
    const int*    __restrict__ gid)      // [B][M]
{
    const int b = blockIdx.x;
    const int tid = threadIdx.x;
    const int lane = tid & 31, w = tid >> 5;

    __shared__ int   s_gt[TT];
    __shared__ int   s_pr[TT];
    __shared__ float s_mw[TT];   // sums then means
    __shared__ float s_mh[TT];
    __shared__ float s_dw[TT];
    __shared__ float s_dh[TT];
    __shared__ int   s_off[TT];
    __shared__ int   s_cur[TT];
    __shared__ float s_w[NN];
    __shared__ float s_h[NN];
    __shared__ int   s_p[NN];
    __shared__ int   s_wsum[8];
    __shared__ float r_f[32], r_s[32];
    __shared__ int   r_u[32], r_v[32];

    if (tid < TT) {
        s_gt[tid] = 0; s_pr[tid] = 0;
        s_mw[tid] = 0.f; s_mh[tid] = 0.f;
        s_dw[tid] = 0.f; s_dh[tid] = 0.f;
    }
    if (b == 0 && tid == 0) g_done = 0;
    if (tid == 0) { g_match[b] = 0.f; g_fp[b] = 0.f; g_sw[b] = 0; g_traw[b] = 0.f; }
    __syncthreads();

    const int* gidb = gid + b * MM;
    if (tid < MM) atomicAdd(&s_gt[gidb[tid]], 1);

    const int* pidb = pid + b * NN;
    const float4* pb = pboxes + b * NN;
    int nvalid = 0;
    #pragma unroll
    for (int k = 0; k < 2; k++) {
        int i = tid + k * 1024;
        int p = pidb[i];
        float4 bx = pb[i];
        float bw = bx.z - bx.x, bh = bx.w - bx.y;
        s_w[i] = bw; s_h[i] = bh; s_p[i] = p;
        if (p > 0) {
            atomicAdd(&s_pr[p], 1);
            atomicAdd(&s_mw[p], bw);
            atomicAdd(&s_mh[p], bh);
            nvalid++;
        }
    }
    __syncthreads();

    // means; prefix scan of gt counts (threads 0..255 = warps 0..7)
    int c_gt = 0, vinc = 0;
    if (tid < TT) {
        int c = s_pr[tid];
        float cs = fmaxf((float)c, 1.f);
        s_mw[tid] = s_mw[tid] / cs;
        s_mh[tid] = s_mh[tid] / cs;
        g_pr_cnt[b][tid] = c;
        c_gt = s_gt[tid];
        g_gt_cnt[b][tid] = c_gt;
        vinc = c_gt;
        #pragma unroll
        for (int o = 1; o < 32; o <<= 1) {
            int n = __shfl_up_sync(0xffffffffu, vinc, o);
            if (lane >= o) vinc += n;
        }
        if (lane == 31) s_wsum[w] = vinc;
    }
    __syncthreads();
    if (tid < TT) {
        int woff = 0;
        #pragma unroll
        for (int k = 0; k < 8; k++) if (k < w) woff += s_wsum[k];
        int excl = woff + vinc - c_gt;
        s_off[tid] = excl;
        s_cur[tid] = 0;
        g_csr_off[b][tid] = excl;
    }
    __syncthreads();

    // abs deviation + CSR scatter
    #pragma unroll
    for (int k = 0; k < 2; k++) {
        int i = tid + k * 1024;
        int p = s_p[i];
        if (p > 0) {
            atomicAdd(&s_dw[p], fabsf(s_w[i] - s_mw[p]));
            atomicAdd(&s_dh[p], fabsf(s_h[i] - s_mh[p]));
        }
    }
    if (tid < MM) {
        int t = gidb[tid];
        int pos = s_off[t] + atomicAdd(&s_cur[t], 1);
        g_csr[b][pos] = tid;
    }
    __syncthreads();

    // per-track terms + full-block reduce
    float fn = 0.f, sp = 0.f;
    int nu = 0;
    if (tid < TT) {
        int c  = s_pr[tid];
        int gc = s_gt[tid];
        fn = (gc > 0 && c == 0) ? (float)gc : 0.f;
        nu = (c > 0) ? 1 : 0;
        sp = (c > 1) ? (s_dw[tid] + s_dh[tid]) * SCALE_C / (float)c : 0.f;
    }
    #pragma unroll
    for (int o = 16; o > 0; o >>= 1) {
        fn     += __shfl_down_sync(0xffffffffu, fn, o);
        sp     += __shfl_down_sync(0xffffffffu, sp, o);
        nu     += __shfl_down_sync(0xffffffffu, nu, o);
        nvalid += __shfl_down_sync(0xffffffffu, nvalid, o);
    }
    if (lane == 0) { r_f[w] = fn; r_s[w] = sp; r_u[w] = nu; r_v[w] = nvalid; }
    __syncthreads();
    if (tid == 0) {
        float F = 0.f, S = 0.f; int U = 0, V = 0;
        #pragma unroll
        for (int k = 0; k < 32; k++) { F += r_f[k]; S += r_s[k]; U += r_u[k]; V += r_v[k]; }
        g_fn[b] = F; g_nuni[b] = U; g_nvalid[b] = V;
        g_spatial[b] = (V > 1) ? S / fmaxf((float)U, 1.f) : 0.f;
    }
}

// ======================= K3: IoU sweep + temporal + finalize (fused) =======================
// grid (8, BB), 256 threads, one pred per thread over all M gts.
__global__ __launch_bounds__(256) void k3_iou(
    const float4* __restrict__ pboxes,
    const float4* __restrict__ gboxes,
    const int*    __restrict__ pid,
    const int*    __restrict__ gid,
    float* __restrict__ out)
{
    const int b = blockIdx.y;
    const int tid = threadIdx.x;

    __shared__ float4 s_gb[MM];          // gt boxes            16 KB
    __shared__ float  s_a2[MM];          // a2 or +INF           4 KB
    __shared__ int    s_p[NN];           // pred ids             8 KB
    __shared__ float  s_cx[NN];          //                      8 KB
    __shared__ float  s_cy[NN];          //                      8 KB
    __shared__ int    s_last;

    const float4* gb4  = gboxes + b * MM;
    const int*    gidb = gid + b * MM;
    const float4* pb4  = pboxes + b * NN;
    const int*    pidb = pid + b * NN;

    #pragma unroll
    for (int k = 0; k < 4; k++) {
        int j = tid + k * 256;
        float4 g = gb4[j];
        s_gb[j] = g;
        float a2 = fmaxf(g.z - g.x, 0.f) * fmaxf(g.w - g.y, 0.f);
        bool prb = (g_pr_cnt[b][gidb[j]] > 0);
        s_a2[j] = prb ? a2 : __int_as_float(0x7f800000);   // +INF disables hi-test
    }
    #pragma unroll
    for (int k = 0; k < 8; k++) {
        int i = tid + k * 256;
        float4 bx = pb4[i];
        s_p[i]  = pidb[i];
        s_cx[i] = (bx.x + bx.z) * 0.5f;
        s_cy[i] = (bx.y + bx.w) * 0.5f;
    }
    __syncthreads();

    const int i = blockIdx.x * 256 + tid;
    const int p = s_p[i];

    float matchv = 0.f, fpv = 0.f;
    int swc = 0;
    if (p > 0) {
        float4 pbx = pb4[i];
        const float px1 = pbx.x, py1 = pbx.y, px2 = pbx.z, py2 = pbx.w;
        const float a1 = fmaxf(px2 - px1, 0.f) * fmaxf(py2 - py1, 0.f);

        // hot loop: count hi-IoU pairs against eligible tracks (incl. own; fixed below)
        const float4* a2v = (const float4*)s_a2;
        for (int j4 = 0; j4 < MM / 4; j4++) {
            float4 aq = a2v[j4];
            int jb = j4 * 4;
            float i0 = inter_area(px1, py1, px2, py2, s_gb[jb + 0]);
            float i1 = inter_area(px1, py1, px2, py2, s_gb[jb + 1]);
            float i2 = inter_area(px1, py1, px2, py2, s_gb[jb + 2]);
            float i3 = inter_area(px1, py1, px2, py2, s_gb[jb + 3]);
            swc += (fmaf(3.f, i0, -a1) > aq.x);
            swc += (fmaf(3.f, i1, -a1) > aq.y);
            swc += (fmaf(3.f, i2, -a1) > aq.z);
            swc += (fmaf(3.f, i3, -a1) > aq.w);
        }

        // own-track gts only (CSR): max IoU + subtract same-track hi pairs
        int gc = g_gt_cnt[b][p];
        if (gc > 0) {
            int off = g_csr_off[b][p];
            float bn = 0.f, bd = 1.f;
            for (int k = 0; k < gc; k++) {
                int j = g_csr[b][off + k];
                float4 g = s_gb[j];
                float inter = inter_area(px1, py1, px2, py2, g);
                float a2 = s_a2[j];                 // true a2 (own track => prflag)
                float uni = a1 + a2 - inter;
                if (inter * bd > bn * uni) { bn = inter; bd = uni; }
                swc -= (fmaf(3.f, inter, -a1) > a2);  // identical hi-test
            }
            matchv = 1.f - __fdividef(bn, bd);
        } else {
            fpv = 1.f;
        }
    }

    // warp reduce + per-warp atomics
    #pragma unroll
    for (int o = 16; o > 0; o >>= 1) {
        matchv += __shfl_down_sync(0xffffffffu, matchv, o);
        fpv    += __shfl_down_sync(0xffffffffu, fpv, o);
        swc    += __shfl_down_sync(0xffffffffu, swc, o);
    }
    if ((tid & 31) == 0) {
        atomicAdd(&g_match[b], matchv);
        atomicAdd(&g_fp[b], fpv);
        atomicAdd(&g_sw[b], swc);
    }

    // ---- temporal: each warp handles 4 tracks via ballot scan ----
    {
        const int lane = tid & 31;
        const int wg = blockIdx.x * 8 + (tid >> 5);   // 0..63
        #pragma unroll
        for (int k = 0; k < 4; k++) {
            int t = wg * 4 + k;                        // 0..255 (warp-uniform)
            if (t == 0) continue;
            int cnt = g_pr_cnt[b][t];
            if (cnt <= 2) continue;
            float c0x = 0.f, c0y = 0.f, c1x = 0.f, c1y = 0.f;
            int seen = 0;
            float sa = 0.f;
            for (int base = 0; base < NN; base += 32) {
                int pp = s_p[base + lane];
                unsigned m = __ballot_sync(0xffffffffu, pp == t);
                while (m) {
                    int j = base + (__ffs(m) - 1);
                    m &= m - 1;
                    float cx = s_cx[j];
                    float cy = s_cy[j];
                    if (seen >= 2) {
                        float ax = (cx - 2.f * c1x + c0x) * SCALE_C;
                        float ay = (cy - 2.f * c1y + c0y) * SCALE_C;
                        sa += sqrtf(ax * ax + ay * ay);
                    }
                    c0x = c1x; c0y = c1y; c1x = cx; c1y = cy;
                    seen++;
                }
            }
            if (lane == 0)
                atomicAdd(&g_traw[b], sa / (float)(cnt - 2));
        }
    }

    // ---- last-block-done fused finalize ----
    __syncthreads();
    if (tid == 0) {
        __threadfence();
        int prev = atomicAdd(&g_done, 1);
        s_last = (prev == K3_TOTAL_BLOCKS - 1) ? 1 : 0;
    }
    __syncthreads();
    if (s_last && tid < 32) {
        __threadfence();
        float lt = 0.f, ls = 0.f, lm = 0.f, nt = 0.f;
        if (tid < BB) {
            int bb = tid;
            int nv = g_nvalid[bb];
            int nu = g_nuni[bb];
            float has = (nv > 0) ? 1.f : 0.f;
            float mt  = *((volatile float*)&g_match[bb]);
            float fpb = *((volatile float*)&g_fp[bb]);
            int   sw  = *((volatile int*)&g_sw[bb]);
            float trw = *((volatile float*)&g_traw[bb]);
            float tr = B_FN * g_fn[bb] + mt + G_SW * (float)sw + B_FP * fpb;
            float tmp = (nv > 2) ? trw / fmaxf((float)nu, 1.f) : 0.f;
            lt = tr * has;
            ls = g_spatial[bb] * has;
            lm = tmp * has;
            nt = (float)nu * has;
        }
        #pragma unroll
        for (int o = 16; o > 0; o >>= 1) {
            lt += __shfl_down_sync(0xffffffffu, lt, o);
            ls += __shfl_down_sync(0xffffffffu, ls, o);
            lm += __shfl_down_sync(0xffffffffu, lm, o);
            nt += __shfl_down_sync(0xffffffffu, nt, o);
        }
        if (tid == 0) {
            float norm = (nt > 0.f) ? nt : 1.f;
            lt /= norm; ls /= norm; lm /= norm;
            out[0] = A_TRK * lt + A_SPA * ls + A_TMP * lm;
            out[1] = lt;
            out[2] = ls;
            out[3] = lm;
        }
    }
}

// ======================= launch =======================
extern "C" void kernel_launch(void* const* d_in, const int* in_sizes, int n_in,
                              void* d_out, int out_size)
{
    const float4* pb  = (const float4*)d_in[0];  // pred_boxes [16,2048,4] f32
    const float4* gb  = (const float4*)d_in[1];  // gt_boxes   [16,1024,4] f32
    const int*    pid = (const int*)d_in[2];     // pred_track_ids [16,2048] i32
    const int*    gid = (const int*)d_in[3];     // gt_track_ids   [16,1024] i32
    float* out = (float*)d_out;

    k1_hist<<<BB, 1024>>>(pb, pid, gid);
    k3_iou<<<dim3(K3_BLOCKS_X, BB), 256>>>(pb, gb, pid, gid, out);
}

// round 5
// speedup vs baseline: 3.1810x; 1.2366x over previous
#include <cuda_runtime.h>
#include <cstdint>

#define BB 16
#define NN 2048
#define MM 1024
#define TT 256

#define SCALE_C (4.5392368437151541e-04f)  // 1/sqrt(1920^2+1080^2)
#define A_TRK 2.0f
#define A_SPA 1.5f
#define A_TMP 1.8f
#define B_FP 0.9f
#define B_FN 0.9f
#define G_SW 1.5f

#define K3_BX 32
#define K3_TOTAL_BLOCKS (K3_BX * BB)   // 512
#define PRED_PER_BLK 64                 // NN / K3_BX
#define MSPLIT 4
#define GT_PER_THR (MM / MSPLIT)        // 256

// ---------------- device scratch (no allocations allowed) ----------------
__device__ int   g_gt_cnt[BB][TT];
__device__ int   g_pr_cnt[BB][TT];
__device__ int   g_csr_off[BB][TT];   // exclusive prefix of gt_cnt
__device__ int   g_csr[BB][MM];       // gt indices grouped by track id
__device__ float g_fn[BB];
__device__ int   g_nuni[BB];
__device__ int   g_nvalid[BB];
__device__ float g_match[BB];
__device__ float g_fp[BB];
__device__ int   g_sw[BB];
__device__ float g_spatial[BB];       // finalized in K1
__device__ float g_traw[BB];          // sum over tracks of sa/(cnt-2)
__device__ int   g_done;

__device__ __forceinline__ float inter_area(float px1, float py1, float px2, float py2,
                                            const float4 g) {
    float lx = fmaxf(px1, g.x), ly = fmaxf(py1, g.y);
    float rx = fminf(px2, g.z), ry = fminf(py2, g.w);
    return fmaxf(rx - lx, 0.f) * fmaxf(ry - ly, 0.f);
}

// ======================= K1: hist + fn + counts + spatial + CSR =======================
__global__ __launch_bounds__(1024) void k1_hist(
    const float4* __restrict__ pboxes,   // [B][N]
    const int*    __restrict__ pid,      // [B][N]
    const int*    __restrict__ gid)      // [B][M]
{
    const int b = blockIdx.x;
    const int tid = threadIdx.x;
    const int lane = tid & 31, w = tid >> 5;

    __shared__ int   s_gt[TT];
    __shared__ int   s_pr[TT];
    __shared__ float s_mw[TT];   // sums then means
    __shared__ float s_mh[TT];
    __shared__ float s_dw[TT];
    __shared__ float s_dh[TT];
    __shared__ int   s_off[TT];
    __shared__ int   s_cur[TT];
    __shared__ float s_w[NN];
    __shared__ float s_h[NN];
    __shared__ int   s_p[NN];
    __shared__ int   s_wsum[8];
    __shared__ float r_f[32], r_s[32];
    __shared__ int   r_u[32], r_v[32];

    if (tid < TT) {
        s_gt[tid] = 0; s_pr[tid] = 0;
        s_mw[tid] = 0.f; s_mh[tid] = 0.f;
        s_dw[tid] = 0.f; s_dh[tid] = 0.f;
    }
    if (b == 0 && tid == 0) g_done = 0;
    if (tid == 0) { g_match[b] = 0.f; g_fp[b] = 0.f; g_sw[b] = 0; g_traw[b] = 0.f; }
    __syncthreads();

    const int* gidb = gid + b * MM;
    if (tid < MM) atomicAdd(&s_gt[gidb[tid]], 1);

    const int* pidb = pid + b * NN;
    const float4* pb = pboxes + b * NN;
    int nvalid = 0;
    #pragma unroll
    for (int k = 0; k < 2; k++) {
        int i = tid + k * 1024;
        int p = pidb[i];
        float4 bx = pb[i];
        float bw = bx.z - bx.x, bh = bx.w - bx.y;
        s_w[i] = bw; s_h[i] = bh; s_p[i] = p;
        if (p > 0) {
            atomicAdd(&s_pr[p], 1);
            atomicAdd(&s_mw[p], bw);
            atomicAdd(&s_mh[p], bh);
            nvalid++;
        }
    }
    __syncthreads();

    // means; prefix scan of gt counts (threads 0..255 = warps 0..7)
    int c_gt = 0, vinc = 0;
    if (tid < TT) {
        int c = s_pr[tid];
        float cs = fmaxf((float)c, 1.f);
        s_mw[tid] = s_mw[tid] / cs;
        s_mh[tid] = s_mh[tid] / cs;
        g_pr_cnt[b][tid] = c;
        c_gt = s_gt[tid];
        g_gt_cnt[b][tid] = c_gt;
        vinc = c_gt;
        #pragma unroll
        for (int o = 1; o < 32; o <<= 1) {
            int n = __shfl_up_sync(0xffffffffu, vinc, o);
            if (lane >= o) vinc += n;
        }
        if (lane == 31) s_wsum[w] = vinc;
    }
    __syncthreads();
    if (tid < TT) {
        int woff = 0;
        #pragma unroll
        for (int k = 0; k < 8; k++) if (k < w) woff += s_wsum[k];
        int excl = woff + vinc - c_gt;
        s_off[tid] = excl;
        s_cur[tid] = 0;
        g_csr_off[b][tid] = excl;
    }
    __syncthreads();

    // abs deviation + CSR scatter
    #pragma unroll
    for (int k = 0; k < 2; k++) {
        int i = tid + k * 1024;
        int p = s_p[i];
        if (p > 0) {
            atomicAdd(&s_dw[p], fabsf(s_w[i] - s_mw[p]));
            atomicAdd(&s_dh[p], fabsf(s_h[i] - s_mh[p]));
        }
    }
    if (tid < MM) {
        int t = gidb[tid];
        int pos = s_off[t] + atomicAdd(&s_cur[t], 1);
        g_csr[b][pos] = tid;
    }
    __syncthreads();

    // per-track terms + full-block reduce
    float fn = 0.f, sp = 0.f;
    int nu = 0;
    if (tid < TT) {
        int c  = s_pr[tid];
        int gc = s_gt[tid];
        fn = (gc > 0 && c == 0) ? (float)gc : 0.f;
        nu = (c > 0) ? 1 : 0;
        sp = (c > 1) ? (s_dw[tid] + s_dh[tid]) * SCALE_C / (float)c : 0.f;
    }
    #pragma unroll
    for (int o = 16; o > 0; o >>= 1) {
        fn     += __shfl_down_sync(0xffffffffu, fn, o);
        sp     += __shfl_down_sync(0xffffffffu, sp, o);
        nu     += __shfl_down_sync(0xffffffffu, nu, o);
        nvalid += __shfl_down_sync(0xffffffffu, nvalid, o);
    }
    if (lane == 0) { r_f[w] = fn; r_s[w] = sp; r_u[w] = nu; r_v[w] = nvalid; }
    __syncthreads();
    if (tid == 0) {
        float F = 0.f, S = 0.f; int U = 0, V = 0;
        #pragma unroll
        for (int k = 0; k < 32; k++) { F += r_f[k]; S += r_s[k]; U += r_u[k]; V += r_v[k]; }
        g_fn[b] = F; g_nuni[b] = U; g_nvalid[b] = V;
        g_spatial[b] = (V > 1) ? S / fmaxf((float)U, 1.f) : 0.f;
    }
}

// ======================= K3: IoU sweep + temporal + finalize (fused) =======================
// grid (32, BB), 256 threads. 64 preds/block, 4-way M split per pred.
__global__ __launch_bounds__(256, 4) void k3_iou(
    const float4* __restrict__ pboxes,
    const float4* __restrict__ gboxes,
    const int*    __restrict__ pid,
    const int*    __restrict__ gid,
    float* __restrict__ out)
{
    const int b = blockIdx.y;
    const int tid = threadIdx.x;

    __shared__ __align__(16) float4 s_gb[MM];   // gt boxes   16 KB
    __shared__ __align__(16) float  s_a2[MM];   // a2 or +INF  4 KB
    __shared__ int s_p[NN];                     // pred ids    8 KB
    __shared__ int s_last;

    const float4* gb4  = gboxes + b * MM;
    const int*    gidb = gid + b * MM;
    const float4* pb4  = pboxes + b * NN;
    const int*    pidb = pid + b * NN;

    #pragma unroll
    for (int k = 0; k < 4; k++) {
        int j = tid + k * 256;
        float4 g = gb4[j];
        s_gb[j] = g;
        float a2 = fmaxf(g.z - g.x, 0.f) * fmaxf(g.w - g.y, 0.f);
        bool prb = (g_pr_cnt[b][gidb[j]] > 0);
        s_a2[j] = prb ? a2 : __int_as_float(0x7f800000);   // +INF disables hi-test
    }
    #pragma unroll
    for (int k = 0; k < 8; k++) {
        int i = tid + k * 256;
        s_p[i] = pidb[i];
    }
    __syncthreads();

    const int pred_l = tid & (PRED_PER_BLK - 1);
    const int msplit = tid >> 6;                         // warp-uniform (warp>>1)
    const int i = blockIdx.x * PRED_PER_BLK + pred_l;
    const int p = s_p[i];

    float matchv = 0.f, fpv = 0.f;
    int swc = 0;
    if (p > 0) {
        float4 pbx = pb4[i];
        const float px1 = pbx.x, py1 = pbx.y, px2 = pbx.z, py2 = pbx.w;
        const float a1 = fmaxf(px2 - px1, 0.f) * fmaxf(py2 - py1, 0.f);

        // hot loop: count hi-IoU pairs over this thread's quarter of M
        const float4* a2v = (const float4*)s_a2;
        const int j4b = msplit * (GT_PER_THR / 4);
        #pragma unroll 2
        for (int j4 = j4b; j4 < j4b + GT_PER_THR / 4; j4++) {
            float4 aq = a2v[j4];
            int jb = j4 * 4;
            float i0 = inter_area(px1, py1, px2, py2, s_gb[jb + 0]);
            float i1 = inter_area(px1, py1, px2, py2, s_gb[jb + 1]);
            float i2 = inter_area(px1, py1, px2, py2, s_gb[jb + 2]);
            float i3 = inter_area(px1, py1, px2, py2, s_gb[jb + 3]);
            swc += (fmaf(3.f, i0, -a1) > aq.x);
            swc += (fmaf(3.f, i1, -a1) > aq.y);
            swc += (fmaf(3.f, i2, -a1) > aq.z);
            swc += (fmaf(3.f, i3, -a1) > aq.w);
        }

        // own-track gts only (CSR), msplit 0 only: max IoU + subtract same-track hi pairs
        if (msplit == 0) {
            int gc = g_gt_cnt[b][p];
            if (gc > 0) {
                int off = g_csr_off[b][p];
                float bn = 0.f, bd = 1.f;
                for (int k = 0; k < gc; k++) {
                    int j = g_csr[b][off + k];
                    float4 g = s_gb[j];
                    float inter = inter_area(px1, py1, px2, py2, g);
                    float a2 = s_a2[j];                 // own track => prflag => true a2
                    float uni = a1 + a2 - inter;
                    if (inter * bd > bn * uni) { bn = inter; bd = uni; }
                    swc -= (fmaf(3.f, inter, -a1) > a2);  // identical hi-test
                }
                matchv = 1.f - __fdividef(bn, bd);
            } else {
                fpv = 1.f;
            }
        }
    }

    // warp reduce + per-warp atomics (swc additive across msplits)
    #pragma unroll
    for (int o = 16; o > 0; o >>= 1) {
        matchv += __shfl_down_sync(0xffffffffu, matchv, o);
        fpv    += __shfl_down_sync(0xffffffffu, fpv, o);
        swc    += __shfl_down_sync(0xffffffffu, swc, o);
    }
    if ((tid & 31) == 0) {
        atomicAdd(&g_match[b], matchv);
        atomicAdd(&g_fp[b], fpv);
        atomicAdd(&g_sw[b], swc);
    }

    // ---- temporal: one track per warp via ballot scan ----
    {
        const int lane = tid & 31;
        const int t = blockIdx.x * 8 + (tid >> 5);   // 0..255, warp-uniform
        int cnt = (t > 0) ? g_pr_cnt[b][t] : 0;
        if (cnt > 2) {
            float c0x = 0.f, c0y = 0.f, c1x = 0.f, c1y = 0.f;
            int seen = 0;
            float sa = 0.f;
            for (int base = 0; base < NN; base += 32) {
                int pp = s_p[base + lane];
                unsigned m = __ballot_sync(0xffffffffu, pp == t);
                while (m) {
                    int j = base + (__ffs(m) - 1);
                    m &= m - 1;
                    float4 bx = pb4[j];                 // rare: L1/L2 hit
                    float cx = (bx.x + bx.z) * 0.5f;
                    float cy = (bx.y + bx.w) * 0.5f;
                    if (seen >= 2) {
                        float ax = (cx - 2.f * c1x + c0x) * SCALE_C;
                        float ay = (cy - 2.f * c1y + c0y) * SCALE_C;
                        sa += sqrtf(ax * ax + ay * ay);
                    }
                    c0x = c1x; c0y = c1y; c1x = cx; c1y = cy;
                    seen++;
                }
            }
            if (lane == 0)
                atomicAdd(&g_traw[b], sa / (float)(cnt - 2));
        }
    }

    // ---- last-block-done fused finalize ----
    __syncthreads();
    if (tid == 0) {
        __threadfence();
        int prev = atomicAdd(&g_done, 1);
        s_last = (prev == K3_TOTAL_BLOCKS - 1) ? 1 : 0;
    }
    __syncthreads();
    if (s_last && tid < 32) {
        __threadfence();
        float lt = 0.f, ls = 0.f, lm = 0.f, nt = 0.f;
        if (tid < BB) {
            int bb = tid;
            int nv = g_nvalid[bb];
            int nu = g_nuni[bb];
            float has = (nv > 0) ? 1.f : 0.f;
            float mt  = *((volatile float*)&g_match[bb]);
            float fpb = *((volatile float*)&g_fp[bb]);
            int   sw  = *((volatile int*)&g_sw[bb]);
            float trw = *((volatile float*)&g_traw[bb]);
            float tr = B_FN * g_fn[bb] + mt + G_SW * (float)sw + B_FP * fpb;
            float tmp = (nv > 2) ? trw / fmaxf((float)nu, 1.f) : 0.f;
            lt = tr * has;
            ls = g_spatial[bb] * has;
            lm = tmp * has;
            nt = (float)nu * has;
        }
        #pragma unroll
        for (int o = 16; o > 0; o >>= 1) {
            lt += __shfl_down_sync(0xffffffffu, lt, o);
            ls += __shfl_down_sync(0xffffffffu, ls, o);
            lm += __shfl_down_sync(0xffffffffu, lm, o);
            nt += __shfl_down_sync(0xffffffffu, nt, o);
        }
        if (tid == 0) {
            float norm = (nt > 0.f) ? nt : 1.f;
            lt /= norm; ls /= norm; lm /= norm;
            out[0] = A_TRK * lt + A_SPA * ls + A_TMP * lm;
            out[1] = lt;
            out[2] = ls;
            out[3] = lm;
        }
    }
}

// ======================= launch =======================
extern "C" void kernel_launch(void* const* d_in, const int* in_sizes, int n_in,
                              void* d_out, int out_size)
{
    const float4* pb  = (const float4*)d_in[0];  // pred_boxes [16,2048,4] f32
    const float4* gb  = (const float4*)d_in[1];  // gt_boxes   [16,1024,4] f32
    const int*    pid = (const int*)d_in[2];     // pred_track_ids [16,2048] i32
    const int*    gid = (const int*)d_in[3];     // gt_track_ids   [16,1024] i32
    float* out = (float*)d_out;

    k1_hist<<<BB, 1024>>>(pb, pid, gid);
    k3_iou<<<dim3(K3_BX, BB), 256>>>(pb, gb, pid, gid, out);
}